// round 10
// baseline (speedup 1.0000x reference)
#include <cuda_runtime.h>
#include <math.h>

#define BB 32
#define TT 2048
#define FF 128
#define UU 256
#define U3 768
#define NF 20

// ---------------- scratch (device globals: allocation-free) ----------------
__device__ float g_xw_f[(size_t)BB * TT * U3];   // 201 MB
__device__ float g_xw_b[(size_t)BB * TT * U3];   // 201 MB
__device__ float g_h0[(size_t)BB * TT * 2 * UU]; // 134 MB
__device__ float g_h1[(size_t)BB * TT * 2 * UU]; // 134 MB
__device__ float g_rt[4][U3 * UU];               // transposed recurrent kernels

// ---------------- f32x2 packed-math helpers ----------------
__device__ __forceinline__ unsigned long long fma2(unsigned long long a,
                                                   unsigned long long b,
                                                   unsigned long long c) {
    unsigned long long d;
    asm("fma.rn.f32x2 %0, %1, %2, %3;" : "=l"(d) : "l"(a), "l"(b), "l"(c));
    return d;
}
__device__ __forceinline__ unsigned long long pack2(float x, float y) {
    unsigned long long u;
    asm("mov.b64 %0, {%1, %2};" : "=l"(u) : "f"(x), "f"(y));
    return u;
}
__device__ __forceinline__ float2 u2f(unsigned long long u) {
    float2 f;
    asm("mov.b64 {%0, %1}, %2;" : "=f"(f.x), "=f"(f.y) : "l"(u));
    return f;
}
__device__ __forceinline__ float sigmoidf(float x) {
    return 1.0f / (1.0f + expf(-x));
}

// ---------------- transpose rec kernel: [256,768] -> [768,256] ----------------
__global__ void __launch_bounds__(256) transpose_r_kernel(const float* __restrict__ in,
                                                          float* __restrict__ out) {
    int idx = blockIdx.x * 256 + threadIdx.x;   // 768 blocks -> 196608 threads
    int k = idx / U3;
    int c = idx % U3;
    out[c * UU + k] = in[idx];
}

// ---------------- GEMM + bias: C[M,N] = A[M,K] @ W[K,N] + bias[N] ----------------
// BM=BN=128, BK=8, 256 threads, 8x8 per thread (as 4 row-pairs via f32x2)
__global__ void __launch_bounds__(256) gemm_bias_kernel(
    const float* __restrict__ A, const float* __restrict__ W,
    const float* __restrict__ bias, float* __restrict__ C,
    int M, int N, int K) {
    __shared__ float As[8][128];
    __shared__ float Bs[8][128];
    const int tid = threadIdx.x;
    const int bm = blockIdx.y * 128;
    const int bn = blockIdx.x * 128;
    const int tx = tid & 15, ty = tid >> 4;

    const int arow = tid >> 1;          // 0..127
    const int acol = (tid & 1) * 4;     // 0 or 4
    const int wrow = tid >> 5;          // 0..7
    const int wcol = (tid & 31) * 4;    // 0..124

    const float* Aptr = A + (size_t)(bm + arow) * K + acol;
    const float* Wptr = W + (size_t)wrow * N + bn + wcol;

    unsigned long long acc[4][8];
#pragma unroll
    for (int p = 0; p < 4; ++p)
#pragma unroll
        for (int c = 0; c < 8; ++c) acc[p][c] = 0ull;

    for (int kt = 0; kt < K; kt += 8) {
        float4 a4 = *reinterpret_cast<const float4*>(Aptr + kt);
        float4 w4 = *reinterpret_cast<const float4*>(Wptr + (size_t)kt * N);
        As[acol + 0][arow] = a4.x;
        As[acol + 1][arow] = a4.y;
        As[acol + 2][arow] = a4.z;
        As[acol + 3][arow] = a4.w;
        *reinterpret_cast<float4*>(&Bs[wrow][wcol]) = w4;
        __syncthreads();
#pragma unroll
        for (int k = 0; k < 8; ++k) {
            const unsigned long long* a2 =
                reinterpret_cast<const unsigned long long*>(&As[k][ty * 8]);
            float4 b0 = *reinterpret_cast<const float4*>(&Bs[k][tx * 8]);
            float4 b1 = *reinterpret_cast<const float4*>(&Bs[k][tx * 8 + 4]);
            unsigned long long a20 = a2[0], a21 = a2[1], a22 = a2[2], a23 = a2[3];
            unsigned long long bb[8];
            bb[0] = pack2(b0.x, b0.x); bb[1] = pack2(b0.y, b0.y);
            bb[2] = pack2(b0.z, b0.z); bb[3] = pack2(b0.w, b0.w);
            bb[4] = pack2(b1.x, b1.x); bb[5] = pack2(b1.y, b1.y);
            bb[6] = pack2(b1.z, b1.z); bb[7] = pack2(b1.w, b1.w);
#pragma unroll
            for (int c = 0; c < 8; ++c) {
                acc[0][c] = fma2(a20, bb[c], acc[0][c]);
                acc[1][c] = fma2(a21, bb[c], acc[1][c]);
                acc[2][c] = fma2(a22, bb[c], acc[2][c]);
                acc[3][c] = fma2(a23, bb[c], acc[3][c]);
            }
        }
        __syncthreads();
    }

    float bv[8];
#pragma unroll
    for (int c = 0; c < 8; ++c) bv[c] = bias[bn + tx * 8 + c];
#pragma unroll
    for (int p = 0; p < 4; ++p) {
        float r0[8], r1[8];
#pragma unroll
        for (int c = 0; c < 8; ++c) {
            float2 v = u2f(acc[p][c]);
            r0[c] = v.x + bv[c];
            r1[c] = v.y + bv[c];
        }
        size_t row0 = (size_t)(bm + ty * 8 + 2 * p) * N + bn + tx * 8;
        size_t row1 = row0 + N;
        *reinterpret_cast<float4*>(&C[row0])     = make_float4(r0[0], r0[1], r0[2], r0[3]);
        *reinterpret_cast<float4*>(&C[row0 + 4]) = make_float4(r0[4], r0[5], r0[6], r0[7]);
        *reinterpret_cast<float4*>(&C[row1])     = make_float4(r1[0], r1[1], r1[2], r1[3]);
        *reinterpret_cast<float4*>(&C[row1 + 4]) = make_float4(r1[4], r1[5], r1[6], r1[7]);
    }
}

// ---------------- GRU recurrence ----------------
// grid = 32: blockIdx>>4 = dir (0 fwd, 1 bwd), blockIdx&15 = batch group (2 batches).
// 256 threads: thread i owns unit i. h in smem, R transposed [col][k] for packed loads.
__global__ void __launch_bounds__(256) gru_rec_kernel(
    const float* __restrict__ xwF, const float* __restrict__ xwB,
    const float* __restrict__ RtF, const float* __restrict__ RtB,
    const float* __restrict__ b1F, const float* __restrict__ b1B,
    float* __restrict__ out) {
    const int i = threadIdx.x;
    const int dir = blockIdx.x >> 4;
    const int grp = blockIdx.x & 15;
    const float* __restrict__ xw = dir ? xwB : xwF;
    const float* __restrict__ Rt = dir ? RtB : RtF;
    const float* __restrict__ b1 = dir ? b1B : b1F;

    __shared__ __align__(16) float sh[2][UU];

    const float bz = b1[i], br = b1[UU + i], bh = b1[2 * UU + i];

    const ulonglong2* __restrict__ Rz =
        reinterpret_cast<const ulonglong2*>(Rt + (size_t)i * UU);
    const ulonglong2* __restrict__ Rr =
        reinterpret_cast<const ulonglong2*>(Rt + (size_t)(UU + i) * UU);
    const ulonglong2* __restrict__ Rh =
        reinterpret_cast<const ulonglong2*>(Rt + (size_t)(2 * UU + i) * UU);

    float h0r = 0.0f, h1r = 0.0f;
    sh[0][i] = 0.0f;
    sh[1][i] = 0.0f;
    __syncthreads();

    const size_t rowb0 = (size_t)(grp * 2 + 0) * TT;
    const size_t rowb1 = (size_t)(grp * 2 + 1) * TT;

    for (int s = 0; s < TT; ++s) {
        const int t = dir ? (TT - 1 - s) : s;
        const float* xw0 = xw + (rowb0 + t) * (size_t)U3;
        const float* xw1 = xw + (rowb1 + t) * (size_t)U3;
        const float xz0 = xw0[i], xr0 = xw0[UU + i], xh0 = xw0[2 * UU + i];
        const float xz1 = xw1[i], xr1 = xw1[UU + i], xh1 = xw1[2 * UU + i];

        unsigned long long az0 = 0, az1 = 0, ar0 = 0, ar1 = 0, ah0 = 0, ah1 = 0;
        const ulonglong2* __restrict__ Ha = reinterpret_cast<const ulonglong2*>(sh[0]);
        const ulonglong2* __restrict__ Hb = reinterpret_cast<const ulonglong2*>(sh[1]);
#pragma unroll 4
        for (int v = 0; v < UU / 4; ++v) {
            ulonglong2 rz = Rz[v], rr = Rr[v], rh = Rh[v];
            ulonglong2 ha = Ha[v], hb = Hb[v];
            az0 = fma2(rz.x, ha.x, az0); az0 = fma2(rz.y, ha.y, az0);
            ar0 = fma2(rr.x, ha.x, ar0); ar0 = fma2(rr.y, ha.y, ar0);
            ah0 = fma2(rh.x, ha.x, ah0); ah0 = fma2(rh.y, ha.y, ah0);
            az1 = fma2(rz.x, hb.x, az1); az1 = fma2(rz.y, hb.y, az1);
            ar1 = fma2(rr.x, hb.x, ar1); ar1 = fma2(rr.y, hb.y, ar1);
            ah1 = fma2(rh.x, hb.x, ah1); ah1 = fma2(rh.y, hb.y, ah1);
        }
        float2 vz0 = u2f(az0), vr0 = u2f(ar0), vh0 = u2f(ah0);
        float2 vz1 = u2f(az1), vr1 = u2f(ar1), vh1 = u2f(ah1);

        // batch 0
        float z0 = sigmoidf(xz0 + vz0.x + vz0.y + bz);
        float r0 = sigmoidf(xr0 + vr0.x + vr0.y + br);
        float hh0 = fmaxf(xh0 + r0 * (vh0.x + vh0.y + bh), 0.0f);
        float hn0 = z0 * h0r + (1.0f - z0) * hh0;
        // batch 1
        float z1 = sigmoidf(xz1 + vz1.x + vz1.y + bz);
        float r1 = sigmoidf(xr1 + vr1.x + vr1.y + br);
        float hh1 = fmaxf(xh1 + r1 * (vh1.x + vh1.y + bh), 0.0f);
        float hn1 = z1 * h1r + (1.0f - z1) * hh1;

        out[(rowb0 + t) * (size_t)(2 * UU) + dir * UU + i] = hn0;
        out[(rowb1 + t) * (size_t)(2 * UU) + dir * UU + i] = hn1;
        h0r = hn0;
        h1r = hn1;

        __syncthreads();                 // all reads of sh done
        sh[0][i] = h0r;
        sh[1][i] = h1r;
        __syncthreads();                 // new h visible
    }
}

// ---------------- dense + softmax: out[row,:] = softmax(h[row,:] @ Wd + bd) ----------------
__global__ void __launch_bounds__(128) dense_softmax_kernel(
    const float* __restrict__ H, const float* __restrict__ Wd,
    const float* __restrict__ bd, float* __restrict__ out) {
    __shared__ float sW[2 * UU * NF];    // 512*20 floats = 40 KB
    __shared__ float sb[NF];
    const int tid = threadIdx.x;
    for (int idx = tid; idx < 2 * UU * NF; idx += 128) sW[idx] = Wd[idx];
    if (tid < NF) sb[tid] = bd[tid];
    __syncthreads();

    const int lane = tid & 31, warp = tid >> 5;
    const int lane2 = (lane < NF) ? lane : 0;
    const size_t row0 = (size_t)blockIdx.x * 64 + warp * 16;

    for (int rr = 0; rr < 16; ++rr) {
        const size_t row = row0 + rr;
        const float* h = H + row * (size_t)(2 * UU);
        float acc = sb[lane2];
#pragma unroll 4
        for (int k = 0; k < 2 * UU; k += 4) {
            float4 h4 = *reinterpret_cast<const float4*>(h + k);
            acc += h4.x * sW[(k + 0) * NF + lane2];
            acc += h4.y * sW[(k + 1) * NF + lane2];
            acc += h4.z * sW[(k + 2) * NF + lane2];
            acc += h4.w * sW[(k + 3) * NF + lane2];
        }
        float m = (lane < NF) ? acc : -3.4e38f;
        for (int o = 16; o; o >>= 1) m = fmaxf(m, __shfl_xor_sync(0xFFFFFFFFu, m, o));
        float e = (lane < NF) ? expf(acc - m) : 0.0f;
        float ssum = e;
        for (int o = 16; o; o >>= 1) ssum += __shfl_xor_sync(0xFFFFFFFFu, ssum, o);
        if (lane < NF) out[row * NF + lane] = e / ssum;
    }
}

// ---------------- launch ----------------
extern "C" void kernel_launch(void* const* d_in, const int* in_sizes, int n_in,
                              void* d_out, int out_size) {
    const float* x    = (const float*)d_in[0];
    const float* k0f  = (const float*)d_in[1];
    const float* rk0f = (const float*)d_in[2];
    const float* b0f  = (const float*)d_in[3];
    const float* k0b  = (const float*)d_in[4];
    const float* rk0b = (const float*)d_in[5];
    const float* b0b  = (const float*)d_in[6];
    const float* k1f  = (const float*)d_in[7];
    const float* rk1f = (const float*)d_in[8];
    const float* b1f  = (const float*)d_in[9];
    const float* k1b  = (const float*)d_in[10];
    const float* rk1b = (const float*)d_in[11];
    const float* b1b  = (const float*)d_in[12];
    const float* Wd   = (const float*)d_in[13];
    const float* bd   = (const float*)d_in[14];
    float* out = (float*)d_out;

    float *xwf, *xwb, *h0, *h1, *rt;
    cudaGetSymbolAddress((void**)&xwf, g_xw_f);
    cudaGetSymbolAddress((void**)&xwb, g_xw_b);
    cudaGetSymbolAddress((void**)&h0, g_h0);
    cudaGetSymbolAddress((void**)&h1, g_h1);
    cudaGetSymbolAddress((void**)&rt, g_rt);
    float* rt0f = rt + 0 * (U3 * UU);
    float* rt0b = rt + 1 * (U3 * UU);
    float* rt1f = rt + 2 * (U3 * UU);
    float* rt1b = rt + 3 * (U3 * UU);

    // transpose recurrent kernels (tiny, once per replay)
    transpose_r_kernel<<<768, 256>>>(rk0f, rt0f);
    transpose_r_kernel<<<768, 256>>>(rk0b, rt0b);
    transpose_r_kernel<<<768, 256>>>(rk1f, rt1f);
    transpose_r_kernel<<<768, 256>>>(rk1b, rt1b);

    dim3 gg(U3 / 128, (BB * TT) / 128);  // (6, 512)

    // layer 0 input projections (bias row 0 folded in)
    gemm_bias_kernel<<<gg, 256>>>(x, k0f, b0f, xwf, BB * TT, U3, FF);
    gemm_bias_kernel<<<gg, 256>>>(x, k0b, b0b, xwb, BB * TT, U3, FF);
    // layer 0 recurrence (fwd + bwd) -> h0 [B,T,512]
    gru_rec_kernel<<<32, 256>>>(xwf, xwb, rt0f, rt0b, b0f + U3, b0b + U3, h0);

    // layer 1 input projections (reuse xw buffers)
    gemm_bias_kernel<<<gg, 256>>>(h0, k1f, b1f, xwf, BB * TT, U3, 2 * UU);
    gemm_bias_kernel<<<gg, 256>>>(h0, k1b, b1b, xwb, BB * TT, U3, 2 * UU);
    // layer 1 recurrence -> h1 [B,T,512]
    gru_rec_kernel<<<32, 256>>>(xwf, xwb, rt1f, rt1b, b1f + U3, b1b + U3, h1);

    // dense softmax head
    dense_softmax_kernel<<<(BB * TT) / 64, 128>>>(h1, Wd, bd, out);
}

// round 12
// speedup vs baseline: 7.0771x; 7.0771x over previous
#include <cuda_runtime.h>
#include <stdint.h>
#include <math.h>

#define BB 32
#define TT 2048
#define FF 128
#define UU 256
#define U3 768
#define NF 20

#define CLUSTER 8
#define NB 4              // batches per cluster
#define GRU_THREADS 192   // (col in 0..95) x (k-half in 0..1)

// ---------------- scratch (device globals: allocation-free) ----------------
__device__ float g_xw_f[(size_t)BB * TT * U3];   // 201 MB
__device__ float g_xw_b[(size_t)BB * TT * U3];   // 201 MB
__device__ float g_h0[(size_t)BB * TT * 2 * UU]; // 134 MB
__device__ float g_h1[(size_t)BB * TT * 2 * UU]; // 134 MB

// ---------------- f32x2 packed-math helpers ----------------
__device__ __forceinline__ unsigned long long fma2(unsigned long long a,
                                                   unsigned long long b,
                                                   unsigned long long c) {
    unsigned long long d;
    asm("fma.rn.f32x2 %0, %1, %2, %3;" : "=l"(d) : "l"(a), "l"(b), "l"(c));
    return d;
}
__device__ __forceinline__ unsigned long long pack2(float x, float y) {
    unsigned long long u;
    asm("mov.b64 %0, {%1, %2};" : "=l"(u) : "f"(x), "f"(y));
    return u;
}
__device__ __forceinline__ float2 u2f(unsigned long long u) {
    float2 f;
    asm("mov.b64 {%0, %1}, %2;" : "=f"(f.x), "=f"(f.y) : "l"(u));
    return f;
}
__device__ __forceinline__ float sigmoidf(float x) {
    return 1.0f / (1.0f + expf(-x));
}

// ---------------- GEMM + bias: C[M,N] = A[M,K] @ W[K,N] + bias[N] ----------------
// BM=BN=128, BK=8, 256 threads, 8x8 per thread (as 4 row-pairs via f32x2)
__global__ void __launch_bounds__(256) gemm_bias_kernel(
    const float* __restrict__ A, const float* __restrict__ W,
    const float* __restrict__ bias, float* __restrict__ C,
    int M, int N, int K) {
    __shared__ float As[8][128];
    __shared__ float Bs[8][128];
    const int tid = threadIdx.x;
    const int bm = blockIdx.y * 128;
    const int bn = blockIdx.x * 128;
    const int tx = tid & 15, ty = tid >> 4;

    const int arow = tid >> 1;          // 0..127
    const int acol = (tid & 1) * 4;     // 0 or 4
    const int wrow = tid >> 5;          // 0..7
    const int wcol = (tid & 31) * 4;    // 0..124

    const float* Aptr = A + (size_t)(bm + arow) * K + acol;
    const float* Wptr = W + (size_t)wrow * N + bn + wcol;

    unsigned long long acc[4][8];
#pragma unroll
    for (int p = 0; p < 4; ++p)
#pragma unroll
        for (int c = 0; c < 8; ++c) acc[p][c] = 0ull;

    for (int kt = 0; kt < K; kt += 8) {
        float4 a4 = *reinterpret_cast<const float4*>(Aptr + kt);
        float4 w4 = *reinterpret_cast<const float4*>(Wptr + (size_t)kt * N);
        As[acol + 0][arow] = a4.x;
        As[acol + 1][arow] = a4.y;
        As[acol + 2][arow] = a4.z;
        As[acol + 3][arow] = a4.w;
        *reinterpret_cast<float4*>(&Bs[wrow][wcol]) = w4;
        __syncthreads();
#pragma unroll
        for (int k = 0; k < 8; ++k) {
            const unsigned long long* a2 =
                reinterpret_cast<const unsigned long long*>(&As[k][ty * 8]);
            float4 b0 = *reinterpret_cast<const float4*>(&Bs[k][tx * 8]);
            float4 b1 = *reinterpret_cast<const float4*>(&Bs[k][tx * 8 + 4]);
            unsigned long long a20 = a2[0], a21 = a2[1], a22 = a2[2], a23 = a2[3];
            unsigned long long bb[8];
            bb[0] = pack2(b0.x, b0.x); bb[1] = pack2(b0.y, b0.y);
            bb[2] = pack2(b0.z, b0.z); bb[3] = pack2(b0.w, b0.w);
            bb[4] = pack2(b1.x, b1.x); bb[5] = pack2(b1.y, b1.y);
            bb[6] = pack2(b1.z, b1.z); bb[7] = pack2(b1.w, b1.w);
#pragma unroll
            for (int c = 0; c < 8; ++c) {
                acc[0][c] = fma2(a20, bb[c], acc[0][c]);
                acc[1][c] = fma2(a21, bb[c], acc[1][c]);
                acc[2][c] = fma2(a22, bb[c], acc[2][c]);
                acc[3][c] = fma2(a23, bb[c], acc[3][c]);
            }
        }
        __syncthreads();
    }

    float bv[8];
#pragma unroll
    for (int c = 0; c < 8; ++c) bv[c] = bias[bn + tx * 8 + c];
#pragma unroll
    for (int p = 0; p < 4; ++p) {
        float r0[8], r1[8];
#pragma unroll
        for (int c = 0; c < 8; ++c) {
            float2 v = u2f(acc[p][c]);
            r0[c] = v.x + bv[c];
            r1[c] = v.y + bv[c];
        }
        size_t row0 = (size_t)(bm + ty * 8 + 2 * p) * N + bn + tx * 8;
        size_t row1 = row0 + N;
        *reinterpret_cast<float4*>(&C[row0])     = make_float4(r0[0], r0[1], r0[2], r0[3]);
        *reinterpret_cast<float4*>(&C[row0 + 4]) = make_float4(r0[4], r0[5], r0[6], r0[7]);
        *reinterpret_cast<float4*>(&C[row1])     = make_float4(r1[0], r1[1], r1[2], r1[3]);
        *reinterpret_cast<float4*>(&C[row1 + 4]) = make_float4(r1[4], r1[5], r1[6], r1[7]);
    }
}

// ---------------- clustered GRU recurrence ----------------
// Grid = 128 CTAs, cluster of 8. cid = blockIdx.x>>3 in 0..15:
//   dir = cid>>3 (0 fwd, 1 bwd), grp = cid&7 -> batches [grp*4, grp*4+4).
// CTA rank c owns units [c*32, c*32+32) for all 3 gates (96 columns of R).
// R slice (96 KB) lives in SMEM for the whole kernel. h (256 x 4 batches)
// is double-buffered in every CTA's SMEM, updated each step via DSMEM stores.
//
// SMEM float layout:
//   sRs [64 k4][96 col] float4  : 24576 floats (96 KB), element (k4*96+col)*4+(k&3)
//   sh  [2 parity][NB][256]     : 2048 floats (8 KB)
//   sp  [96 col][2 half][NB]    : 768 floats (3 KB)
#define SRS_FLOATS (64 * 96 * 4)
#define SH_FLOATS  (2 * NB * 256)
#define SP_FLOATS  (96 * 2 * NB)
#define GRU_SMEM_BYTES ((SRS_FLOATS + SH_FLOATS + SP_FLOATS) * 4)

__global__ void __launch_bounds__(GRU_THREADS, 1) __cluster_dims__(CLUSTER, 1, 1)
gru_cluster_kernel(const float* __restrict__ xwF, const float* __restrict__ xwB,
                   const float* __restrict__ rkF, const float* __restrict__ rkB,
                   const float* __restrict__ b1F, const float* __restrict__ b1B,
                   float* __restrict__ out) {
    extern __shared__ float smem[];
    float* sRs = smem;
    float* sh  = smem + SRS_FLOATS;
    float* sp  = sh + SH_FLOATS;

    const int tid = threadIdx.x;
    unsigned int rank;
    asm("mov.u32 %0, %%cluster_ctarank;" : "=r"(rank));
    const int cid = blockIdx.x >> 3;
    const int dir = cid >> 3;
    const int grp = cid & 7;
    const float* __restrict__ xw = dir ? xwB : xwF;
    const float* __restrict__ rk = dir ? rkB : rkF;
    const float* __restrict__ b1 = dir ? b1B : b1F;

    // ---- stage this CTA's 96-column R slice into SMEM (one time) ----
    {
        int w = tid >> 5, lane = tid & 31;
        int g  = w % 3;        // gate
        int kp = w / 3;        // k half
        int cg = g * UU + (int)rank * 32 + lane;    // global R column
        for (int k = kp * 128; k < kp * 128 + 128; ++k) {
            float v = rk[(size_t)k * U3 + cg];      // rk is k-major [256][768]
            sRs[(((k >> 2) * 96 + g * 32 + lane) << 2) + (k & 3)] = v;
        }
    }
    for (int i = tid; i < SH_FLOATS; i += GRU_THREADS) sh[i] = 0.0f;
    __syncthreads();
    // all CTAs' h buffers zeroed before any peer can write into them
    asm volatile("barrier.cluster.arrive.aligned;" ::: "memory");
    asm volatile("barrier.cluster.wait.aligned;" ::: "memory");

    const int half = tid / 96;
    const int col  = tid % 96;
    const int u    = tid & 31;        // combine threads (tid<128)
    const int b    = tid >> 5;        // combine threads: batch 0..3
    const int idxu = (int)rank * 32 + u;

    float bz = 0.f, br = 0.f, bh = 0.f;
    if (tid < 128) {
        bz = b1[idxu];
        br = b1[UU + idxu];
        bh = b1[2 * UU + idxu];
    }
    const size_t browT = (size_t)(grp * NB + b) * TT;
    float hprev = 0.0f;

    unsigned int smem_u32;
    asm("{ .reg .u64 t; cvta.to.shared.u64 t, %1; cvt.u32.u64 %0, t; }"
        : "=r"(smem_u32) : "l"(smem));
    const unsigned int hsBase = smem_u32 + (unsigned int)SRS_FLOATS * 4u;

    const ulonglong2* __restrict__ Rp =
        reinterpret_cast<const ulonglong2*>(sRs) + half * 32 * 96 + col;

    for (int s = 0; s < TT; ++s) {
        const int t = dir ? (TT - 1 - s) : s;
        const int p = s & 1;

        // x-projection loads for this step (latency hidden behind dot loop)
        float xz = 0.f, xr = 0.f, xh = 0.f;
        if (tid < 128) {
            const float* xrow = xw + (browT + t) * (size_t)U3;
            xz = __ldg(xrow + idxu);
            xr = __ldg(xrow + UU + idxu);
            xh = __ldg(xrow + 2 * UU + idxu);
        }

        // dot products: acc_b = sum_k R[col][k] * h[b][k] over this thread's k-half
        const ulonglong2* __restrict__ Hp =
            reinterpret_cast<const ulonglong2*>(sh) + p * NB * 64 + half * 32;
        unsigned long long a0 = 0, a1 = 0, a2 = 0, a3 = 0;
#pragma unroll 4
        for (int kk = 0; kk < 32; ++kk) {
            ulonglong2 r  = Rp[kk * 96];
            ulonglong2 h0 = Hp[kk];
            ulonglong2 h1 = Hp[64 + kk];
            ulonglong2 h2 = Hp[128 + kk];
            ulonglong2 h3 = Hp[192 + kk];
            a0 = fma2(r.x, h0.x, a0); a0 = fma2(r.y, h0.y, a0);
            a1 = fma2(r.x, h1.x, a1); a1 = fma2(r.y, h1.y, a1);
            a2 = fma2(r.x, h2.x, a2); a2 = fma2(r.y, h2.y, a2);
            a3 = fma2(r.x, h3.x, a3); a3 = fma2(r.y, h3.y, a3);
        }
        float2 v;
        v = u2f(a0); sp[(col * 2 + half) * NB + 0] = v.x + v.y;
        v = u2f(a1); sp[(col * 2 + half) * NB + 1] = v.x + v.y;
        v = u2f(a2); sp[(col * 2 + half) * NB + 2] = v.x + v.y;
        v = u2f(a3); sp[(col * 2 + half) * NB + 3] = v.x + v.y;
        __syncthreads();

        if (tid < 128) {
            float dz = sp[((0 * 32 + u) * 2 + 0) * NB + b] + sp[((0 * 32 + u) * 2 + 1) * NB + b];
            float dr = sp[((1 * 32 + u) * 2 + 0) * NB + b] + sp[((1 * 32 + u) * 2 + 1) * NB + b];
            float dh = sp[((2 * 32 + u) * 2 + 0) * NB + b] + sp[((2 * 32 + u) * 2 + 1) * NB + b];
            float z  = sigmoidf(xz + dz + bz);
            float r  = sigmoidf(xr + dr + br);
            float hh = fmaxf(xh + r * (dh + bh), 0.0f);
            float hn = z * hprev + (1.0f - z) * hh;
            hprev = hn;
            out[(browT + t) * (size_t)(2 * UU) + dir * UU + idxu] = hn;

            // broadcast h_new to all 8 CTAs' hs[(p^1)][b][idxu]
            unsigned int myaddr = hsBase +
                (((unsigned int)(((p ^ 1) * NB + b) * 256 + idxu)) << 2);
#pragma unroll
            for (int rr = 0; rr < CLUSTER; ++rr) {
                unsigned int ra;
                asm("mapa.shared::cluster.u32 %0, %1, %2;"
                    : "=r"(ra) : "r"(myaddr), "r"(rr));
                asm volatile("st.shared::cluster.f32 [%0], %1;"
                             :: "r"(ra), "f"(hn));
            }
        }
        // release our h writes / acquire peers' h writes for next step
        asm volatile("barrier.cluster.arrive.aligned;" ::: "memory");
        asm volatile("barrier.cluster.wait.aligned;" ::: "memory");
    }
}

// ---------------- dense + softmax ----------------
__global__ void __launch_bounds__(128) dense_softmax_kernel(
    const float* __restrict__ H, const float* __restrict__ Wd,
    const float* __restrict__ bd, float* __restrict__ out) {
    __shared__ float sW[2 * UU * NF];
    __shared__ float sb[NF];
    const int tid = threadIdx.x;
    for (int idx = tid; idx < 2 * UU * NF; idx += 128) sW[idx] = Wd[idx];
    if (tid < NF) sb[tid] = bd[tid];
    __syncthreads();

    const int lane = tid & 31, warp = tid >> 5;
    const int lane2 = (lane < NF) ? lane : 0;
    const size_t row0 = (size_t)blockIdx.x * 64 + warp * 16;

    for (int rr = 0; rr < 16; ++rr) {
        const size_t row = row0 + rr;
        const float* h = H + row * (size_t)(2 * UU);
        float acc = sb[lane2];
#pragma unroll 4
        for (int k = 0; k < 2 * UU; k += 4) {
            float4 h4 = *reinterpret_cast<const float4*>(h + k);
            acc += h4.x * sW[(k + 0) * NF + lane2];
            acc += h4.y * sW[(k + 1) * NF + lane2];
            acc += h4.z * sW[(k + 2) * NF + lane2];
            acc += h4.w * sW[(k + 3) * NF + lane2];
        }
        float m = (lane < NF) ? acc : -3.4e38f;
        for (int o = 16; o; o >>= 1) m = fmaxf(m, __shfl_xor_sync(0xFFFFFFFFu, m, o));
        float e = (lane < NF) ? expf(acc - m) : 0.0f;
        float ssum = e;
        for (int o = 16; o; o >>= 1) ssum += __shfl_xor_sync(0xFFFFFFFFu, ssum, o);
        if (lane < NF) out[row * NF + lane] = e / ssum;
    }
}

// ---------------- launch ----------------
extern "C" void kernel_launch(void* const* d_in, const int* in_sizes, int n_in,
                              void* d_out, int out_size) {
    const float* x    = (const float*)d_in[0];
    const float* k0f  = (const float*)d_in[1];
    const float* rk0f = (const float*)d_in[2];
    const float* b0f  = (const float*)d_in[3];
    const float* k0b  = (const float*)d_in[4];
    const float* rk0b = (const float*)d_in[5];
    const float* b0b  = (const float*)d_in[6];
    const float* k1f  = (const float*)d_in[7];
    const float* rk1f = (const float*)d_in[8];
    const float* b1f  = (const float*)d_in[9];
    const float* k1b  = (const float*)d_in[10];
    const float* rk1b = (const float*)d_in[11];
    const float* b1b  = (const float*)d_in[12];
    const float* Wd   = (const float*)d_in[13];
    const float* bd   = (const float*)d_in[14];
    float* out = (float*)d_out;

    float *xwf, *xwb, *h0, *h1;
    cudaGetSymbolAddress((void**)&xwf, g_xw_f);
    cudaGetSymbolAddress((void**)&xwb, g_xw_b);
    cudaGetSymbolAddress((void**)&h0, g_h0);
    cudaGetSymbolAddress((void**)&h1, g_h1);

    cudaFuncSetAttribute(gru_cluster_kernel,
                         cudaFuncAttributeMaxDynamicSharedMemorySize,
                         GRU_SMEM_BYTES);

    dim3 gg(U3 / 128, (BB * TT) / 128);  // (6, 512)

    // layer 0 input projections (bias row 0 folded in)
    gemm_bias_kernel<<<gg, 256>>>(x, k0f, b0f, xwf, BB * TT, U3, FF);
    gemm_bias_kernel<<<gg, 256>>>(x, k0b, b0b, xwb, BB * TT, U3, FF);
    // layer 0 recurrence (fwd + bwd, clustered) -> h0 [B,T,512]
    gru_cluster_kernel<<<128, GRU_THREADS, GRU_SMEM_BYTES>>>(
        xwf, xwb, rk0f, rk0b, b0f + U3, b0b + U3, h0);

    // layer 1 input projections (reuse xw buffers)
    gemm_bias_kernel<<<gg, 256>>>(h0, k1f, b1f, xwf, BB * TT, U3, 2 * UU);
    gemm_bias_kernel<<<gg, 256>>>(h0, k1b, b1b, xwb, BB * TT, U3, 2 * UU);
    // layer 1 recurrence -> h1 [B,T,512]
    gru_cluster_kernel<<<128, GRU_THREADS, GRU_SMEM_BYTES>>>(
        xwf, xwb, rk1f, rk1b, b1f + U3, b1b + U3, h1);

    // dense softmax head
    dense_softmax_kernel<<<(BB * TT) / 64, 128>>>(h1, Wd, bd, out);
}